// round 4
// baseline (speedup 1.0000x reference)
#include <cuda_runtime.h>
#include <cuda_bf16.h>
#include <math.h>

// Problem constants (fixed by the dataset).
#define NN 50000
#define DD 256
#define KK 64
#define HH 8
#define OO 64
#define EE 1600000
#define HK (HH*KK)   // 512

// ---------------- scratch (device globals; no allocation allowed) ----------
__device__ float    g_x2  [NN*DD];            // x @ layer_W + b           51.2 MB
__device__ float    g_Wall[DD*HK];            // packed heads_W [256,512]
__device__ float    g_hall[(size_t)NN*HK];    // per-head features        102.4 MB
__device__ int      g_srci[EE];
__device__ int      g_dsti[EE];
__device__ float    g_ssrc[NN*HH];
__device__ float    g_sdst[NN*HH];
__device__ unsigned g_menc[HH*NN];            // encoded segment max
__device__ float    g_den [HH*NN];
__device__ float    g_w   [(size_t)HH*EE];    // softmax numerators        51.2 MB
__device__ float    g_out1[(size_t)NN*HK];    // aggregated -> elu -> hcat 102.4 MB
__device__ float    g_h2  [NN*OO];
__device__ float    g_s2s [NN];
__device__ float    g_s2d [NN];
__device__ unsigned g_menc2[NN];
__device__ float    g_den2 [NN];
__device__ float    g_w2  [EE];
__device__ float    g_out2[NN*OO];
__device__ int      g_edges_is64;

// ---------------- helpers ---------------------------------------------------
__device__ __forceinline__ unsigned fenc(float f) {
    unsigned u = __float_as_uint(f);
    return u ^ (unsigned)(((int)u >> 31) | 0x80000000);
}
__device__ __forceinline__ float fdec(unsigned u) {
    unsigned m = (u & 0x80000000u) ? 0x80000000u : 0xFFFFFFFFu;
    return __uint_as_float(u ^ m);
}
__device__ __forceinline__ float lrelu(float x) { return x > 0.f ? x : 0.2f * x; }

__device__ __forceinline__ void red_add_v4(float* p, float a, float b, float c, float d) {
    asm volatile("red.global.add.v4.f32 [%0], {%1,%2,%3,%4};"
                 :: "l"(p), "f"(a), "f"(b), "f"(c), "f"(d) : "memory");
}

// ---------------- edge dtype detection + conversion --------------------------
// If the buffer is int64, every odd 32-bit word is a high half (all zero for
// node ids < 2^31). If int32, odd words are random node ids (virtually never
// all zero across 2048 samples). Deterministic for given input data.
__global__ void k_detect_edges(const unsigned* __restrict__ raw) {
    __shared__ int nz;
    if (threadIdx.x == 0) nz = 0;
    __syncthreads();
    for (int i = threadIdx.x; i < 2048; i += 256)
        if (raw[2*i + 1] != 0u) atomicOr(&nz, 1);
    __syncthreads();
    if (threadIdx.x == 0) g_edges_is64 = (nz == 0) ? 1 : 0;
}

__global__ void k_conv_edges(const void* __restrict__ ed) {
    int i = blockIdx.x * 256 + threadIdx.x;
    if (i >= EE) return;
    int s, d;
    if (g_edges_is64) {
        const long long* p = (const long long*)ed;
        s = (int)p[i];
        d = (int)p[(size_t)EE + i];
    } else {
        const int* p = (const int*)ed;
        s = p[i];
        d = p[EE + i];
    }
    s = min(max(s, 0), NN - 1);
    d = min(max(d, 0), NN - 1);
    g_srci[i] = s;
    g_dsti[i] = d;
}

__global__ void k_pack_wall(const float* __restrict__ hw) {
    int i = blockIdx.x * 256 + threadIdx.x;   // i < 256*512
    if (i < DD*HK) {
        int d = i / HK, j = i % HK;
        int h = j >> 6, kk = j & 63;
        g_Wall[i] = hw[h*(DD*KK) + d*KK + kk];
    }
}

// ---------------- SGEMM: C[M,N] = A[M,K] @ B[K,N] (+bias) -------------------
template<int BM, int BN, int BK, int TM, int TN, bool BIAS>
__global__ __launch_bounds__((BM/TM)*(BN/TN))
void k_sgemm(int M, int N, int K,
             const float* __restrict__ A, const float* __restrict__ B,
             const float* __restrict__ bias, float* __restrict__ C) {
    constexpr int THREADS = (BM/TM)*(BN/TN);
    __shared__ float As[BK][BM];
    __shared__ float Bs[BK][BN];
    const int tid = threadIdx.x;
    const int bm0 = blockIdx.y * BM;
    const int bn0 = blockIdx.x * BN;
    const int tx = tid % (BN/TN);
    const int ty = tid / (BN/TN);

    float acc[TM][TN];
    #pragma unroll
    for (int i = 0; i < TM; i++)
        #pragma unroll
        for (int j = 0; j < TN; j++) acc[i][j] = 0.f;

    for (int k0 = 0; k0 < K; k0 += BK) {
        constexpr int AV = BM*BK/4, BV = BK*BN/4;
        #pragma unroll
        for (int it = 0; it < AV/THREADS; it++) {
            int i = tid + it*THREADS;
            int row = i / (BK/4);
            int kc  = (i % (BK/4)) * 4;
            float4 v = make_float4(0.f, 0.f, 0.f, 0.f);
            int gr = bm0 + row;
            if (gr < M) v = *(const float4*)&A[(size_t)gr*K + k0 + kc];
            As[kc+0][row] = v.x; As[kc+1][row] = v.y;
            As[kc+2][row] = v.z; As[kc+3][row] = v.w;
        }
        #pragma unroll
        for (int it = 0; it < BV/THREADS; it++) {
            int i = tid + it*THREADS;
            int row = i / (BN/4);
            int col = (i % (BN/4)) * 4;
            *(float4*)&Bs[row][col] = *(const float4*)&B[(size_t)(k0+row)*N + bn0 + col];
        }
        __syncthreads();
        #pragma unroll
        for (int kk = 0; kk < BK; kk++) {
            float a[TM], b[TN];
            #pragma unroll
            for (int i = 0; i < TM; i++) a[i] = As[kk][ty*TM + i];
            #pragma unroll
            for (int j = 0; j < TN; j++) b[j] = Bs[kk][tx*TN + j];
            #pragma unroll
            for (int i = 0; i < TM; i++)
                #pragma unroll
                for (int j = 0; j < TN; j++)
                    acc[i][j] = fmaf(a[i], b[j], acc[i][j]);
        }
        __syncthreads();
    }

    #pragma unroll
    for (int i = 0; i < TM; i++) {
        int gr = bm0 + ty*TM + i;
        if (gr >= M) continue;
        #pragma unroll
        for (int j = 0; j < TN; j += 4) {
            int gc = bn0 + tx*TN + j;
            float4 v;
            v.x = acc[i][j+0]; v.y = acc[i][j+1];
            v.z = acc[i][j+2]; v.w = acc[i][j+3];
            if (BIAS) {
                v.x += bias[gc+0]; v.y += bias[gc+1];
                v.z += bias[gc+2]; v.w += bias[gc+3];
            }
            *(float4*)&C[(size_t)gr*N + gc] = v;
        }
    }
}

// ---------------- attention projections -------------------------------------
// s_src[n][h] = dot(hall[n, h*64 : h*64+64], a_h[0:64]); s_dst with a_h[64:128]
__global__ void k_proj_heads(const float* __restrict__ ha) {
    int n = blockIdx.x;
    int w = threadIdx.x >> 5, l = threadIdx.x & 31;
    const float* row = g_hall + (size_t)n*HK + w*KK;
    const float* a = ha + w*(2*KK);
    float x0 = row[l], x1 = row[l+32];
    float s = x0*a[l]    + x1*a[l+32];
    float d = x0*a[64+l] + x1*a[96+l];
    #pragma unroll
    for (int off = 16; off; off >>= 1) {
        s += __shfl_xor_sync(0xffffffffu, s, off);
        d += __shfl_xor_sync(0xffffffffu, d, off);
    }
    if (l == 0) { g_ssrc[n*HH + w] = s; g_sdst[n*HH + w] = d; }
}

__global__ void k_proj_end(const float* __restrict__ ea) {
    int w = threadIdx.x >> 5, l = threadIdx.x & 31;
    int n = blockIdx.x * 8 + w;
    if (n >= NN) return;
    const float* row = g_h2 + (size_t)n*OO;
    float x0 = row[l], x1 = row[l+32];
    float s = x0*ea[l]    + x1*ea[l+32];
    float d = x0*ea[64+l] + x1*ea[96+l];
    #pragma unroll
    for (int off = 16; off; off >>= 1) {
        s += __shfl_xor_sync(0xffffffffu, s, off);
        d += __shfl_xor_sync(0xffffffffu, d, off);
    }
    if (l == 0) { g_s2s[n] = s; g_s2d[n] = d; }
}

// ---------------- zeroing ----------------------------------------------------
__global__ void k_zero1() {            // launched with NN*HK threads
    int i = blockIdx.x * 256 + threadIdx.x;
    if (i < HH*NN) { g_menc[i] = 0u; g_den[i] = 0.f; }
    g_out1[i] = 0.f;
}
__global__ void k_zero2() {            // launched with NN*OO threads
    int i = blockIdx.x * 256 + threadIdx.x;
    if (i < NN) { g_menc2[i] = 0u; g_den2[i] = 0.f; }
    g_out2[i] = 0.f;
}

// ---------------- edge passes (head layer) -----------------------------------
__global__ void k_edge_max_h() {
    int e = blockIdx.x * 256 + threadIdx.x;
    if (e >= EE) return;
    int s = g_srci[e], d = g_dsti[e];
    float4 s0 = *(const float4*)&g_ssrc[s*8];
    float4 s1 = *(const float4*)&g_ssrc[s*8+4];
    float4 d0 = *(const float4*)&g_sdst[d*8];
    float4 d1 = *(const float4*)&g_sdst[d*8+4];
    float v[8] = { s0.x+d0.x, s0.y+d0.y, s0.z+d0.z, s0.w+d0.w,
                   s1.x+d1.x, s1.y+d1.y, s1.z+d1.z, s1.w+d1.w };
    #pragma unroll
    for (int h = 0; h < 8; h++)
        atomicMax(&g_menc[h*NN + d], fenc(lrelu(v[h])));
}

__global__ void k_edge_sum_h() {
    int e = blockIdx.x * 256 + threadIdx.x;
    if (e >= EE) return;
    int s = g_srci[e], d = g_dsti[e];
    float4 s0 = *(const float4*)&g_ssrc[s*8];
    float4 s1 = *(const float4*)&g_ssrc[s*8+4];
    float4 d0 = *(const float4*)&g_sdst[d*8];
    float4 d1 = *(const float4*)&g_sdst[d*8+4];
    float v[8] = { s0.x+d0.x, s0.y+d0.y, s0.z+d0.z, s0.w+d0.w,
                   s1.x+d1.x, s1.y+d1.y, s1.z+d1.z, s1.w+d1.w };
    #pragma unroll
    for (int h = 0; h < 8; h++) {
        float m = fdec(g_menc[h*NN + d]);
        float w = expf(lrelu(v[h]) - m);
        g_w[(size_t)h*EE + e] = w;
        atomicAdd(&g_den[h*NN + d], w);
    }
}

// one head per launch -> L2-resident working set (~32 MB)
__global__ void k_edge_agg_h(int h) {
    int gid = blockIdx.x * 256 + threadIdx.x;
    int e = gid >> 4, t = gid & 15;
    if (e >= EE) return;
    int s = g_srci[e], d = g_dsti[e];
    float attn = g_w[(size_t)h*EE + e] / (g_den[h*NN + d] + 1e-16f);
    float4 v = *(const float4*)&g_hall[(size_t)s*HK + h*KK + t*4];
    red_add_v4(&g_out1[(size_t)d*HK + h*KK + t*4],
               v.x*attn, v.y*attn, v.z*attn, v.w*attn);
}

__global__ void k_elu1() {             // NN*HK threads
    int i = blockIdx.x * 256 + threadIdx.x;
    float v = g_out1[i];
    g_out1[i] = v > 0.f ? v : expm1f(v);
}

// ---------------- edge passes (final layer) ----------------------------------
__global__ void k_edge_max_f() {
    int e = blockIdx.x * 256 + threadIdx.x;
    if (e >= EE) return;
    int s = g_srci[e], d = g_dsti[e];
    atomicMax(&g_menc2[d], fenc(lrelu(g_s2s[s] + g_s2d[d])));
}

__global__ void k_edge_sum_f() {
    int e = blockIdx.x * 256 + threadIdx.x;
    if (e >= EE) return;
    int s = g_srci[e], d = g_dsti[e];
    float v = lrelu(g_s2s[s] + g_s2d[d]);
    float w = expf(v - fdec(g_menc2[d]));
    g_w2[e] = w;
    atomicAdd(&g_den2[d], w);
}

__global__ void k_edge_agg_f() {
    int gid = blockIdx.x * 256 + threadIdx.x;
    int e = gid >> 4, t = gid & 15;
    if (e >= EE) return;
    int s = g_srci[e], d = g_dsti[e];
    float attn = g_w2[e] / (g_den2[d] + 1e-16f);
    float4 v = *(const float4*)&g_h2[(size_t)s*OO + t*4];
    red_add_v4(&g_out2[(size_t)d*OO + t*4],
               v.x*attn, v.y*attn, v.z*attn, v.w*attn);
}

// ---------------- epilogue: elu + row softmax --------------------------------
__global__ void k_softmax(float* __restrict__ out) {
    int w = threadIdx.x >> 5, l = threadIdx.x & 31;
    int n = blockIdx.x * 8 + w;
    if (n >= NN) return;
    float x0 = g_out2[(size_t)n*OO + l];
    float x1 = g_out2[(size_t)n*OO + l + 32];
    x0 = x0 > 0.f ? x0 : expm1f(x0);
    x1 = x1 > 0.f ? x1 : expm1f(x1);
    float m = fmaxf(x0, x1);
    #pragma unroll
    for (int off = 16; off; off >>= 1)
        m = fmaxf(m, __shfl_xor_sync(0xffffffffu, m, off));
    float e0 = expf(x0 - m), e1 = expf(x1 - m);
    float sum = e0 + e1;
    #pragma unroll
    for (int off = 16; off; off >>= 1)
        sum += __shfl_xor_sync(0xffffffffu, sum, off);
    float inv = 1.f / sum;
    out[(size_t)n*OO + l]      = e0 * inv;
    out[(size_t)n*OO + l + 32] = e1 * inv;
}

// ---------------- driver ------------------------------------------------------
extern "C" void kernel_launch(void* const* d_in, const int* in_sizes, int n_in,
                              void* d_out, int out_size) {
    const float* x       = (const float*)d_in[0];
    const void*  edges   = d_in[1];               // int32 or int64, detected on device
    const float* layer_W = (const float*)d_in[2];
    const float* layer_b = (const float*)d_in[3];
    const float* heads_W = (const float*)d_in[4];
    const float* heads_a = (const float*)d_in[5];
    const float* end_W   = (const float*)d_in[6];
    const float* end_a   = (const float*)d_in[7];
    float*       out     = (float*)d_out;

    float *p_x2, *p_Wall, *p_hall, *p_out1, *p_h2;
    cudaGetSymbolAddress((void**)&p_x2,   g_x2);
    cudaGetSymbolAddress((void**)&p_Wall, g_Wall);
    cudaGetSymbolAddress((void**)&p_hall, g_hall);
    cudaGetSymbolAddress((void**)&p_out1, g_out1);
    cudaGetSymbolAddress((void**)&p_h2,   g_h2);

    k_detect_edges<<<1, 256>>>((const unsigned*)edges);
    k_conv_edges<<<(EE + 255)/256, 256>>>(edges);
    k_pack_wall<<<(DD*HK + 255)/256, 256>>>(heads_W);

    // x2 = x @ layer_W + b     [50000,256]x[256,256]
    {
        dim3 grid(DD/128, (NN + 127)/128);
        k_sgemm<128,128,8,8,8,true><<<grid, 256>>>(NN, DD, DD, x, layer_W, layer_b, p_x2);
    }
    // hall = x2 @ W_all        [50000,256]x[256,512]
    {
        dim3 grid(HK/128, (NN + 127)/128);
        k_sgemm<128,128,8,8,8,false><<<grid, 256>>>(NN, HK, DD, p_x2, p_Wall, nullptr, p_hall);
    }

    k_proj_heads<<<NN, 256>>>(heads_a);
    k_zero1<<<(NN*HK)/256, 256>>>();
    k_edge_max_h<<<(EE + 255)/256, 256>>>();
    k_edge_sum_h<<<(EE + 255)/256, 256>>>();
    for (int h = 0; h < HH; h++)
        k_edge_agg_h<<<(EE*16)/256, 256>>>(h);
    k_elu1<<<(NN*HK)/256, 256>>>();

    // h2 = hcat @ end_W        [50000,512]x[512,64]
    {
        dim3 grid(OO/64, (NN + 127)/128);
        k_sgemm<128,64,16,8,4,false><<<grid, 256>>>(NN, OO, HK, p_out1, end_W, nullptr, p_h2);
    }

    k_proj_end<<<(NN + 7)/8, 256>>>(end_a);
    k_zero2<<<(NN*OO)/256, 256>>>();
    k_edge_max_f<<<(EE + 255)/256, 256>>>();
    k_edge_sum_f<<<(EE + 255)/256, 256>>>();
    k_edge_agg_f<<<(EE*16)/256, 256>>>();
    k_softmax<<<(NN + 7)/8, 256>>>(out);
}

// round 5
// speedup vs baseline: 1.6399x; 1.6399x over previous
#include <cuda_runtime.h>
#include <cuda_bf16.h>
#include <math.h>

// Problem constants (fixed by the dataset).
#define NN 50000
#define DD 256
#define KK 64
#define HH 8
#define OO 64
#define EE 1600000
#define HK (HH*KK)   // 512

// ---------------- scratch (device globals; no allocation allowed) ----------
__device__ float g_Wall[DD*HK];             // packed heads_W [256,512]
__device__ float g_Wc  [DD*HK];             // layer_W @ Wall
__device__ float g_bc  [HK];                // layer_b @ Wall
__device__ float g_hall[(size_t)NN*HK];     // per-head features  102.4 MB
__device__ int   g_srci[EE];
__device__ int   g_dsti[EE];
__device__ int   g_deg [NN];
__device__ int   g_rowptr[NN+1];
__device__ int   g_off [NN];
__device__ int   g_srt [EE];                // src ids sorted by dst (CSR)
__device__ float g_ssrc[NN*HH];
__device__ float g_sdst[NN*HH];
__device__ float g_m   [NN*HH];             // per-(node,head) max
__device__ float g_dinv[NN*HH];             // per-(node,head) 1/denom
__device__ float g_out1[(size_t)NN*HK];     // aggregated + elu   102.4 MB
__device__ float g_h2  [NN*OO];
__device__ float g_s2s [NN];
__device__ float g_s2d [NN];
__device__ float g_m2  [NN];
__device__ float g_dinv2[NN];
__device__ int   g_edges_is64;

// ---------------- helpers ---------------------------------------------------
__device__ __forceinline__ float lrelu(float x) { return x > 0.f ? x : 0.2f * x; }
__device__ __forceinline__ float elu(float x)   { return x > 0.f ? x : expm1f(x); }

// ---------------- edge dtype detection + conversion --------------------------
__global__ void k_detect_edges(const unsigned* __restrict__ raw) {
    __shared__ int nz;
    if (threadIdx.x == 0) nz = 0;
    __syncthreads();
    for (int i = threadIdx.x; i < 2048; i += 256)
        if (raw[2*i + 1] != 0u) atomicOr(&nz, 1);
    __syncthreads();
    if (threadIdx.x == 0) g_edges_is64 = (nz == 0) ? 1 : 0;
}

__global__ void k_zero_deg() {
    int i = blockIdx.x * 256 + threadIdx.x;
    if (i < NN) g_deg[i] = 0;
}

// convert + histogram of dst
__global__ void k_conv_edges(const void* __restrict__ ed) {
    int i = blockIdx.x * 256 + threadIdx.x;
    if (i >= EE) return;
    int s, d;
    if (g_edges_is64) {
        const long long* p = (const long long*)ed;
        s = (int)p[i];
        d = (int)p[(size_t)EE + i];
    } else {
        const int* p = (const int*)ed;
        s = p[i];
        d = p[EE + i];
    }
    s = min(max(s, 0), NN - 1);
    d = min(max(d, 0), NN - 1);
    g_srci[i] = s;
    g_dsti[i] = d;
    atomicAdd(&g_deg[d], 1);
}

// single-block exclusive scan of deg -> rowptr (and off copy)
__global__ void k_scan() {
    __shared__ int ssum[1024];
    int t = threadIdx.x;
    const int C = (NN + 1023) / 1024;
    int base = t * C;
    int s = 0;
    for (int i = 0; i < C; i++) {
        int idx = base + i;
        if (idx < NN) s += g_deg[idx];
    }
    ssum[t] = s;
    __syncthreads();
    for (int off = 1; off < 1024; off <<= 1) {
        int v = (t >= off) ? ssum[t - off] : 0;
        __syncthreads();
        ssum[t] += v;
        __syncthreads();
    }
    int run = (t == 0) ? 0 : ssum[t - 1];
    for (int i = 0; i < C; i++) {
        int idx = base + i;
        if (idx <= NN) {
            g_rowptr[idx] = run;
            if (idx < NN) { g_off[idx] = run; run += g_deg[idx]; }
        }
    }
}

__global__ void k_scatter() {
    int e = blockIdx.x * 256 + threadIdx.x;
    if (e >= EE) return;
    int d = g_dsti[e];
    int pos = atomicAdd(&g_off[d], 1);
    g_srt[pos] = g_srci[e];
}

// ---------------- weight prep ------------------------------------------------
__global__ void k_pack_wall(const float* __restrict__ hw) {
    int i = blockIdx.x * 256 + threadIdx.x;   // i < 256*512
    if (i < DD*HK) {
        int d = i / HK, j = i % HK;
        int h = j >> 6, kk = j & 63;
        g_Wall[i] = hw[h*(DD*KK) + d*KK + kk];
    }
}

// Wc[i][j] = sum_k layer_W[i][k] * Wall[k][j]
__global__ void k_combine_W(const float* __restrict__ W1) {
    __shared__ float row[DD];
    int i = blockIdx.x;          // 0..255
    int j = threadIdx.x;         // 0..511
    for (int k = threadIdx.x; k < DD; k += blockDim.x) row[k] = W1[i*DD + k];
    __syncthreads();
    float acc = 0.f;
    for (int k = 0; k < DD; k++) acc = fmaf(row[k], g_Wall[k*HK + j], acc);
    g_Wc[i*HK + j] = acc;
}

__global__ void k_combine_b(const float* __restrict__ b) {
    int j = threadIdx.x;         // 512 threads, 1 block
    float acc = 0.f;
    for (int k = 0; k < DD; k++) acc = fmaf(b[k], g_Wall[k*HK + j], acc);
    g_bc[j] = acc;
}

// ---------------- SGEMM: C[M,N] = A[M,K] @ B[K,N] (+bias) -------------------
template<int BM, int BN, int BK, int TM, int TN, bool BIAS>
__global__ __launch_bounds__((BM/TM)*(BN/TN))
void k_sgemm(int M, int N, int K,
             const float* __restrict__ A, const float* __restrict__ B,
             const float* __restrict__ bias, float* __restrict__ C) {
    constexpr int THREADS = (BM/TM)*(BN/TN);
    __shared__ float As[BK][BM];
    __shared__ float Bs[BK][BN];
    const int tid = threadIdx.x;
    const int bm0 = blockIdx.y * BM;
    const int bn0 = blockIdx.x * BN;
    const int tx = tid % (BN/TN);
    const int ty = tid / (BN/TN);

    float acc[TM][TN];
    #pragma unroll
    for (int i = 0; i < TM; i++)
        #pragma unroll
        for (int j = 0; j < TN; j++) acc[i][j] = 0.f;

    for (int k0 = 0; k0 < K; k0 += BK) {
        constexpr int AV = BM*BK/4, BV = BK*BN/4;
        #pragma unroll
        for (int it = 0; it < AV/THREADS; it++) {
            int i = tid + it*THREADS;
            int row = i / (BK/4);
            int kc  = (i % (BK/4)) * 4;
            float4 v = make_float4(0.f, 0.f, 0.f, 0.f);
            int gr = bm0 + row;
            if (gr < M) v = *(const float4*)&A[(size_t)gr*K + k0 + kc];
            As[kc+0][row] = v.x; As[kc+1][row] = v.y;
            As[kc+2][row] = v.z; As[kc+3][row] = v.w;
        }
        #pragma unroll
        for (int it = 0; it < BV/THREADS; it++) {
            int i = tid + it*THREADS;
            int row = i / (BN/4);
            int col = (i % (BN/4)) * 4;
            *(float4*)&Bs[row][col] = *(const float4*)&B[(size_t)(k0+row)*N + bn0 + col];
        }
        __syncthreads();
        #pragma unroll
        for (int kk = 0; kk < BK; kk++) {
            float a[TM], b[TN];
            #pragma unroll
            for (int i = 0; i < TM; i++) a[i] = As[kk][ty*TM + i];
            #pragma unroll
            for (int j = 0; j < TN; j++) b[j] = Bs[kk][tx*TN + j];
            #pragma unroll
            for (int i = 0; i < TM; i++)
                #pragma unroll
                for (int j = 0; j < TN; j++)
                    acc[i][j] = fmaf(a[i], b[j], acc[i][j]);
        }
        __syncthreads();
    }

    #pragma unroll
    for (int i = 0; i < TM; i++) {
        int gr = bm0 + ty*TM + i;
        if (gr >= M) continue;
        #pragma unroll
        for (int j = 0; j < TN; j += 4) {
            int gc = bn0 + tx*TN + j;
            float4 v;
            v.x = acc[i][j+0]; v.y = acc[i][j+1];
            v.z = acc[i][j+2]; v.w = acc[i][j+3];
            if (BIAS) {
                v.x += bias[gc+0]; v.y += bias[gc+1];
                v.z += bias[gc+2]; v.w += bias[gc+3];
            }
            *(float4*)&C[(size_t)gr*N + gc] = v;
        }
    }
}

// ---------------- attention projections -------------------------------------
__global__ void k_proj_heads(const float* __restrict__ ha) {
    int n = blockIdx.x;
    int w = threadIdx.x >> 5, l = threadIdx.x & 31;
    const float* row = g_hall + (size_t)n*HK + w*KK;
    const float* a = ha + w*(2*KK);
    float x0 = row[l], x1 = row[l+32];
    float s = x0*a[l]    + x1*a[l+32];
    float d = x0*a[64+l] + x1*a[96+l];
    #pragma unroll
    for (int off = 16; off; off >>= 1) {
        s += __shfl_xor_sync(0xffffffffu, s, off);
        d += __shfl_xor_sync(0xffffffffu, d, off);
    }
    if (l == 0) { g_ssrc[n*HH + w] = s; g_sdst[n*HH + w] = d; }
}

__global__ void k_proj_end(const float* __restrict__ ea) {
    int w = threadIdx.x >> 5, l = threadIdx.x & 31;
    int n = blockIdx.x * 8 + w;
    if (n >= NN) return;
    const float* row = g_h2 + (size_t)n*OO;
    float x0 = row[l], x1 = row[l+32];
    float s = x0*ea[l]    + x1*ea[l+32];
    float d = x0*ea[64+l] + x1*ea[96+l];
    #pragma unroll
    for (int off = 16; off; off >>= 1) {
        s += __shfl_xor_sync(0xffffffffu, s, off);
        d += __shfl_xor_sync(0xffffffffu, d, off);
    }
    if (l == 0) { g_s2s[n] = s; g_s2d[n] = d; }
}

// ---------------- layer-1 softmax stats (warp per node, all 8 heads) ---------
__global__ void k_stats1() {
    int w = threadIdx.x >> 5, l = threadIdx.x & 31;
    int n = blockIdx.x * 8 + w;
    if (n >= NN) return;
    int r0 = g_rowptr[n], r1 = g_rowptr[n+1];
    float sd[8];
    #pragma unroll
    for (int h = 0; h < 8; h++) sd[h] = g_sdst[n*8 + h];  // broadcast load

    float m[8];
    #pragma unroll
    for (int h = 0; h < 8; h++) m[h] = -1e30f;
    for (int i = r0 + l; i < r1; i += 32) {
        int s = g_srt[i];
        float4 a0 = *(const float4*)&g_ssrc[s*8];
        float4 a1 = *(const float4*)&g_ssrc[s*8 + 4];
        float v[8] = { a0.x, a0.y, a0.z, a0.w, a1.x, a1.y, a1.z, a1.w };
        #pragma unroll
        for (int h = 0; h < 8; h++) m[h] = fmaxf(m[h], lrelu(v[h] + sd[h]));
    }
    #pragma unroll
    for (int h = 0; h < 8; h++)
        #pragma unroll
        for (int off = 16; off; off >>= 1)
            m[h] = fmaxf(m[h], __shfl_xor_sync(0xffffffffu, m[h], off));

    float sum[8];
    #pragma unroll
    for (int h = 0; h < 8; h++) sum[h] = 0.f;
    for (int i = r0 + l; i < r1; i += 32) {
        int s = g_srt[i];
        float4 a0 = *(const float4*)&g_ssrc[s*8];
        float4 a1 = *(const float4*)&g_ssrc[s*8 + 4];
        float v[8] = { a0.x, a0.y, a0.z, a0.w, a1.x, a1.y, a1.z, a1.w };
        #pragma unroll
        for (int h = 0; h < 8; h++) sum[h] += expf(lrelu(v[h] + sd[h]) - m[h]);
    }
    #pragma unroll
    for (int h = 0; h < 8; h++)
        #pragma unroll
        for (int off = 16; off; off >>= 1)
            sum[h] += __shfl_xor_sync(0xffffffffu, sum[h], off);

    if (l == 0) {
        #pragma unroll
        for (int h = 0; h < 8; h++) {
            g_m[n*8 + h]    = m[h];
            g_dinv[n*8 + h] = 1.f / (sum[h] + 1e-16f);
        }
    }
}

// ---------------- layer-1 aggregation (warp per node, one head per launch) ---
__global__ void k_agg1(int h) {
    int w = threadIdx.x >> 5, l = threadIdx.x & 31;
    int n = blockIdx.x * 8 + w;
    if (n >= NN) return;
    int r0 = g_rowptr[n], r1 = g_rowptr[n+1];
    float sd   = g_sdst[n*8 + h];
    float m    = g_m[n*8 + h];
    float dinv = g_dinv[n*8 + h];
    float acc0 = 0.f, acc1 = 0.f;

    int i = r0;
    for (; i + 4 <= r1; i += 4) {
        int s0 = g_srt[i], s1 = g_srt[i+1], s2 = g_srt[i+2], s3 = g_srt[i+3];
        float w0 = expf(lrelu(g_ssrc[s0*8 + h] + sd) - m);
        float w1 = expf(lrelu(g_ssrc[s1*8 + h] + sd) - m);
        float w2 = expf(lrelu(g_ssrc[s2*8 + h] + sd) - m);
        float w3 = expf(lrelu(g_ssrc[s3*8 + h] + sd) - m);
        const float* p0 = &g_hall[(size_t)s0*HK + h*KK];
        const float* p1 = &g_hall[(size_t)s1*HK + h*KK];
        const float* p2 = &g_hall[(size_t)s2*HK + h*KK];
        const float* p3 = &g_hall[(size_t)s3*HK + h*KK];
        float a0 = p0[l], b0 = p0[l+32];
        float a1 = p1[l], b1 = p1[l+32];
        float a2 = p2[l], b2 = p2[l+32];
        float a3 = p3[l], b3 = p3[l+32];
        acc0 = fmaf(w0, a0, acc0); acc1 = fmaf(w0, b0, acc1);
        acc0 = fmaf(w1, a1, acc0); acc1 = fmaf(w1, b1, acc1);
        acc0 = fmaf(w2, a2, acc0); acc1 = fmaf(w2, b2, acc1);
        acc0 = fmaf(w3, a3, acc0); acc1 = fmaf(w3, b3, acc1);
    }
    for (; i < r1; i++) {
        int s = g_srt[i];
        float wgt = expf(lrelu(g_ssrc[s*8 + h] + sd) - m);
        const float* p = &g_hall[(size_t)s*HK + h*KK];
        acc0 = fmaf(wgt, p[l],    acc0);
        acc1 = fmaf(wgt, p[l+32], acc1);
    }
    g_out1[(size_t)n*HK + h*KK + l]      = elu(acc0 * dinv);
    g_out1[(size_t)n*HK + h*KK + l + 32] = elu(acc1 * dinv);
}

// ---------------- layer-2 softmax stats --------------------------------------
__global__ void k_stats2() {
    int w = threadIdx.x >> 5, l = threadIdx.x & 31;
    int n = blockIdx.x * 8 + w;
    if (n >= NN) return;
    int r0 = g_rowptr[n], r1 = g_rowptr[n+1];
    float sd = g_s2d[n];
    float m = -1e30f;
    for (int i = r0 + l; i < r1; i += 32)
        m = fmaxf(m, lrelu(g_s2s[g_srt[i]] + sd));
    #pragma unroll
    for (int off = 16; off; off >>= 1)
        m = fmaxf(m, __shfl_xor_sync(0xffffffffu, m, off));
    float sum = 0.f;
    for (int i = r0 + l; i < r1; i += 32)
        sum += expf(lrelu(g_s2s[g_srt[i]] + sd) - m);
    #pragma unroll
    for (int off = 16; off; off >>= 1)
        sum += __shfl_xor_sync(0xffffffffu, sum, off);
    if (l == 0) { g_m2[n] = m; g_dinv2[n] = 1.f / (sum + 1e-16f); }
}

// ---------------- layer-2 aggregation + elu + row softmax --------------------
__global__ void k_agg2(float* __restrict__ out) {
    int w = threadIdx.x >> 5, l = threadIdx.x & 31;
    int n = blockIdx.x * 8 + w;
    if (n >= NN) return;
    int r0 = g_rowptr[n], r1 = g_rowptr[n+1];
    float sd   = g_s2d[n];
    float m    = g_m2[n];
    float dinv = g_dinv2[n];
    float acc0 = 0.f, acc1 = 0.f;

    int i = r0;
    for (; i + 4 <= r1; i += 4) {
        int s0 = g_srt[i], s1 = g_srt[i+1], s2 = g_srt[i+2], s3 = g_srt[i+3];
        float w0 = expf(lrelu(g_s2s[s0] + sd) - m);
        float w1 = expf(lrelu(g_s2s[s1] + sd) - m);
        float w2 = expf(lrelu(g_s2s[s2] + sd) - m);
        float w3 = expf(lrelu(g_s2s[s3] + sd) - m);
        const float* p0 = &g_h2[(size_t)s0*OO];
        const float* p1 = &g_h2[(size_t)s1*OO];
        const float* p2 = &g_h2[(size_t)s2*OO];
        const float* p3 = &g_h2[(size_t)s3*OO];
        float a0 = p0[l], b0 = p0[l+32];
        float a1 = p1[l], b1 = p1[l+32];
        float a2 = p2[l], b2 = p2[l+32];
        float a3 = p3[l], b3 = p3[l+32];
        acc0 = fmaf(w0, a0, acc0); acc1 = fmaf(w0, b0, acc1);
        acc0 = fmaf(w1, a1, acc0); acc1 = fmaf(w1, b1, acc1);
        acc0 = fmaf(w2, a2, acc0); acc1 = fmaf(w2, b2, acc1);
        acc0 = fmaf(w3, a3, acc0); acc1 = fmaf(w3, b3, acc1);
    }
    for (; i < r1; i++) {
        int s = g_srt[i];
        float wgt = expf(lrelu(g_s2s[s] + sd) - m);
        const float* p = &g_h2[(size_t)s*OO];
        acc0 = fmaf(wgt, p[l],    acc0);
        acc1 = fmaf(wgt, p[l+32], acc1);
    }
    float x0 = elu(acc0 * dinv);
    float x1 = elu(acc1 * dinv);
    // row softmax over 64 cols
    float mx = fmaxf(x0, x1);
    #pragma unroll
    for (int off = 16; off; off >>= 1)
        mx = fmaxf(mx, __shfl_xor_sync(0xffffffffu, mx, off));
    float e0 = expf(x0 - mx), e1 = expf(x1 - mx);
    float sum = e0 + e1;
    #pragma unroll
    for (int off = 16; off; off >>= 1)
        sum += __shfl_xor_sync(0xffffffffu, sum, off);
    float inv = 1.f / sum;
    out[(size_t)n*OO + l]      = e0 * inv;
    out[(size_t)n*OO + l + 32] = e1 * inv;
}

// ---------------- driver ------------------------------------------------------
extern "C" void kernel_launch(void* const* d_in, const int* in_sizes, int n_in,
                              void* d_out, int out_size) {
    const float* x       = (const float*)d_in[0];
    const void*  edges   = d_in[1];               // int32 or int64, detected on device
    const float* layer_W = (const float*)d_in[2];
    const float* layer_b = (const float*)d_in[3];
    const float* heads_W = (const float*)d_in[4];
    const float* heads_a = (const float*)d_in[5];
    const float* end_W   = (const float*)d_in[6];
    const float* end_a   = (const float*)d_in[7];
    float*       out     = (float*)d_out;

    float *p_Wc, *p_bc, *p_hall, *p_out1, *p_h2;
    cudaGetSymbolAddress((void**)&p_Wc,   g_Wc);
    cudaGetSymbolAddress((void**)&p_bc,   g_bc);
    cudaGetSymbolAddress((void**)&p_hall, g_hall);
    cudaGetSymbolAddress((void**)&p_out1, g_out1);
    cudaGetSymbolAddress((void**)&p_h2,   g_h2);

    // --- CSR build -----------------------------------------------------------
    k_detect_edges<<<1, 256>>>((const unsigned*)edges);
    k_zero_deg<<<(NN + 255)/256, 256>>>();
    k_conv_edges<<<(EE + 255)/256, 256>>>(edges);
    k_scan<<<1, 1024>>>();
    k_scatter<<<(EE + 255)/256, 256>>>();

    // --- weight prep: Wc = layer_W @ Wall, bc = layer_b @ Wall ---------------
    k_pack_wall<<<(DD*HK + 255)/256, 256>>>(heads_W);
    k_combine_W<<<DD, HK>>>(layer_W);
    k_combine_b<<<1, HK>>>(layer_b);

    // --- hall = x @ Wc + bc   [50000,256]x[256,512] --------------------------
    {
        dim3 grid(HK/128, (NN + 127)/128);
        k_sgemm<128,128,16,8,8,true><<<grid, 256>>>(NN, HK, DD, x, p_Wc, p_bc, p_hall);
    }

    // --- layer 1 attention ---------------------------------------------------
    k_proj_heads<<<NN, 256>>>(heads_a);
    k_stats1<<<(NN + 7)/8, 256>>>();
    for (int h = 0; h < HH; h++)
        k_agg1<<<(NN + 7)/8, 256>>>(h);

    // --- h2 = hcat @ end_W    [50000,512]x[512,64] ---------------------------
    {
        dim3 grid(OO/64, (NN + 127)/128);
        k_sgemm<128,64,16,8,4,false><<<grid, 256>>>(NN, OO, HK, p_out1, end_W, nullptr, p_h2);
    }

    // --- layer 2 attention + fused epilogue ----------------------------------
    k_proj_end<<<(NN + 7)/8, 256>>>(end_a);
    k_stats2<<<(NN + 7)/8, 256>>>();
    k_agg2<<<(NN + 7)/8, 256>>>(out);
}

// round 8
// speedup vs baseline: 2.9652x; 1.8081x over previous
#include <cuda_runtime.h>
#include <cuda_bf16.h>
#include <math.h>

// Problem constants (fixed by the dataset).
#define NN 50000
#define DD 256
#define KK 64
#define HH 8
#define OO 64
#define EE 1600000
#define HK (HH*KK)   // 512
#define NB 196       // ceil(NN/256)

// ---------------- scratch (device globals; no allocation allowed) ----------
__device__ float g_Wall[DD*HK];             // packed heads_W [256,512]
__device__ float g_Wc  [DD*HK];             // layer_W @ Wall (tf32-rounded)
__device__ float g_bc  [HK];                // layer_b @ Wall
__device__ float g_xt  [(size_t)NN*DD];     // tf32-rounded x
__device__ float g_eWt [HK*OO];             // tf32-rounded end_W
__device__ float g_hall[(size_t)NN*HK];     // per-head features  102.4 MB
__device__ int   g_srci[EE];
__device__ int   g_dsti[EE];
__device__ int   g_deg [NN];
__device__ int   g_excl[NN];
__device__ int   g_part[256];
__device__ int   g_rowptr[NN+1];
__device__ int   g_off [NN];
__device__ int   g_srt [EE];                // src ids sorted by dst (CSR)
__device__ float g_ssrc[NN*HH];
__device__ float g_sdst[NN*HH];
__device__ float g_w   [(size_t)HH*EE];     // normalized attn weights 51.2MB
__device__ float g_out1[(size_t)NN*HK];     // aggregated + elu (tf32-rounded)
__device__ float g_h2  [NN*OO];
__device__ float g_s2s [NN];
__device__ float g_s2d [NN];
__device__ float g_w2  [EE];
__device__ int   g_edges_is64;

// ---------------- helpers ---------------------------------------------------
__device__ __forceinline__ float lrelu(float x) { return x > 0.f ? x : 0.2f * x; }
__device__ __forceinline__ float elu(float x)   { return x > 0.f ? x : expm1f(x); }
__device__ __forceinline__ float tf32r(float x) {
    unsigned u; asm("cvt.rna.tf32.f32 %0, %1;" : "=r"(u) : "f"(x));
    return __uint_as_float(u);
}
__device__ __forceinline__ unsigned smem_u32(const void* p) {
    return (unsigned)__cvta_generic_to_shared(p);
}
__device__ __forceinline__ void cp16(unsigned dst, const void* src, int nbytes) {
    asm volatile("cp.async.cg.shared.global [%0], [%1], 16, %2;"
                 :: "r"(dst), "l"(src), "r"(nbytes));
}
__device__ __forceinline__ void cp_commit() { asm volatile("cp.async.commit_group;"); }
__device__ __forceinline__ void cp_wait0()  { asm volatile("cp.async.wait_group 0;" ::: "memory"); }

// ---------------- edge dtype detection + conversion --------------------------
__global__ void k_detect_edges(const unsigned* __restrict__ raw) {
    __shared__ int nz;
    if (threadIdx.x == 0) nz = 0;
    __syncthreads();
    for (int i = threadIdx.x; i < 2048; i += 256)
        if (raw[2*i + 1] != 0u) atomicOr(&nz, 1);
    __syncthreads();
    if (threadIdx.x == 0) g_edges_is64 = (nz == 0) ? 1 : 0;
}

__global__ void k_zero_deg() {
    int i = blockIdx.x * 256 + threadIdx.x;
    if (i < NN) g_deg[i] = 0;
}

__global__ void k_conv_edges(const void* __restrict__ ed) {
    int i = blockIdx.x * 256 + threadIdx.x;
    if (i >= EE) return;
    int s, d;
    if (g_edges_is64) {
        const long long* p = (const long long*)ed;
        s = (int)p[i];
        d = (int)p[(size_t)EE + i];
    } else {
        const int* p = (const int*)ed;
        s = p[i];
        d = p[EE + i];
    }
    s = min(max(s, 0), NN - 1);
    d = min(max(d, 0), NN - 1);
    g_srci[i] = s;
    g_dsti[i] = d;
    atomicAdd(&g_deg[d], 1);
}

// ---------------- parallel scan (3 tiny kernels) ------------------------------
__global__ void k_scan1() {
    __shared__ int sh[256];
    int t = threadIdx.x;
    int n = blockIdx.x * 256 + t;
    int v = (n < NN) ? g_deg[n] : 0;
    sh[t] = v;
    __syncthreads();
    #pragma unroll
    for (int off = 1; off < 256; off <<= 1) {
        int x = (t >= off) ? sh[t - off] : 0;
        __syncthreads();
        sh[t] += x;
        __syncthreads();
    }
    if (n < NN) g_excl[n] = sh[t] - v;
    if (t == 255) g_part[blockIdx.x] = sh[255];
}
__global__ void k_scan2() {
    __shared__ int sh[256];
    int t = threadIdx.x;
    int v = (t < NB) ? g_part[t] : 0;
    sh[t] = v;
    __syncthreads();
    #pragma unroll
    for (int off = 1; off < 256; off <<= 1) {
        int x = (t >= off) ? sh[t - off] : 0;
        __syncthreads();
        sh[t] += x;
        __syncthreads();
    }
    g_part[t] = sh[t] - v;   // exclusive
}
__global__ void k_scan3() {
    int n = blockIdx.x * 256 + threadIdx.x;
    if (n < NN) {
        int r = g_excl[n] + g_part[n >> 8];
        g_rowptr[n] = r;
        g_off[n] = r;
    }
    if (n == 0) g_rowptr[NN] = EE;
}

__global__ void k_scatter() {
    int e = blockIdx.x * 256 + threadIdx.x;
    if (e >= EE) return;
    int d = g_dsti[e];
    int pos = atomicAdd(&g_off[d], 1);
    g_srt[pos] = g_srci[e];
}

// ---------------- weight prep ------------------------------------------------
__global__ void k_pack_wall(const float* __restrict__ hw) {
    int i = blockIdx.x * 256 + threadIdx.x;
    if (i < DD*HK) {
        int d = i / HK, j = i % HK;
        int h = j >> 6, kk = j & 63;
        g_Wall[i] = hw[h*(DD*KK) + d*KK + kk];
    }
}

__global__ void k_combine_W(const float* __restrict__ W1) {
    __shared__ float row[DD];
    int i = blockIdx.x;
    int j = threadIdx.x;
    for (int k = threadIdx.x; k < DD; k += blockDim.x) row[k] = W1[i*DD + k];
    __syncthreads();
    float acc = 0.f;
    for (int k = 0; k < DD; k++) acc = fmaf(row[k], g_Wall[k*HK + j], acc);
    g_Wc[i*HK + j] = tf32r(acc);
}

__global__ void k_combine_b(const float* __restrict__ b) {
    int j = threadIdx.x;
    float acc = 0.f;
    for (int k = 0; k < DD; k++) acc = fmaf(b[k], g_Wall[k*HK + j], acc);
    g_bc[j] = acc;
}

// round x and end_W to tf32 once (unbiased RNA) so the MMA truncation is exact
__global__ void k_cvt_x(const float* __restrict__ x) {
    size_t i = (size_t)(blockIdx.x) * 256 + threadIdx.x;
    if (i * 4 >= (size_t)NN*DD) return;
    float4 v = *(const float4*)&x[i*4];
    v.x = tf32r(v.x); v.y = tf32r(v.y); v.z = tf32r(v.z); v.w = tf32r(v.w);
    *(float4*)&g_xt[i*4] = v;
}
__global__ void k_cvt_ew(const float* __restrict__ w) {
    int i = blockIdx.x * 256 + threadIdx.x;
    if (i < HK*OO) g_eWt[i] = tf32r(w[i]);
}

// ---------------- tf32 MMA GEMM: C[M,N] = A[M,K] @ B[K,N] (+bias) ------------
// BM=128, BK=32, BN template (128 or 64). 256 threads = 8 warps (2M x 4N).
template<int BN, bool BIAS>
__global__ __launch_bounds__(256, 2)
void k_mma(int M, int N, int K,
           const float* __restrict__ A, const float* __restrict__ B,
           const float* __restrict__ bias, float* __restrict__ C)
{
    constexpr int BM_ = 128, BK_ = 32;
    constexpr int ASTR = BK_ + 4;          // 36: banks (4g+tg) all distinct
    constexpr int BSTR = BN + 8;           // 136/72: banks (8tg+g) all distinct
    constexpr int ASZ = BM_ * ASTR;
    constexpr int BSZ = BK_ * BSTR;
    constexpr int WN = BN / 4;             // warp N tile
    constexpr int NI = WN / 8;             // n8 tiles per warp
    constexpr int BLD = (BK_ * BN / 4) / 256;

    extern __shared__ float sm[];
    float* As0 = sm;                // [2][ASZ], layout [row][k]
    float* Bs0 = sm + 2*ASZ;        // [2][BSZ], layout [k][col]

    const int tid  = threadIdx.x;
    const int lane = tid & 31;
    const int wid  = tid >> 5;
    const int wm = wid & 1, wn = wid >> 1;
    const int g = lane >> 2, tg = lane & 3;

    const int bm0 = blockIdx.y * BM_;
    const int bn0 = blockIdx.x * BN;

    float acc[4][NI][4];
    #pragma unroll
    for (int mi = 0; mi < 4; mi++)
        #pragma unroll
        for (int ni = 0; ni < NI; ni++)
            #pragma unroll
            for (int q = 0; q < 4; q++) acc[mi][ni][q] = 0.f;

    auto load_stage = [&](int kt, int buf) {
        int k0 = kt * BK_;
        float* Asb = As0 + buf*ASZ;
        float* Bsb = Bs0 + buf*BSZ;
        #pragma unroll
        for (int it = 0; it < 4; it++) {
            int i = tid + it*256;
            int row = i >> 3, kc4 = (i & 7) * 4;
            int gr = bm0 + row;
            const float* src = A + (size_t)min(gr, M-1)*K + k0 + kc4;
            cp16(smem_u32(Asb + row*ASTR + kc4), src, (gr < M) ? 16 : 0);
        }
        #pragma unroll
        for (int it = 0; it < BLD; it++) {
            int i = tid + it*256;
            int row = i / (BN/4), c4 = (i % (BN/4)) * 4;
            const float* src = B + (size_t)(k0 + row)*N + bn0 + c4;
            cp16(smem_u32(Bsb + row*BSTR + c4), src, 16);
        }
        cp_commit();
    };

    load_stage(0, 0);
    cp_wait0();
    __syncthreads();

    const int nkt = K / BK_;
    for (int kt = 0; kt < nkt; kt++) {
        int cur = kt & 1;
        if (kt + 1 < nkt) load_stage(kt + 1, cur ^ 1);
        const float* Asb = As0 + cur*ASZ;
        const float* Bsb = Bs0 + cur*BSZ;
        #pragma unroll
        for (int ks = 0; ks < 4; ks++) {
            int kb = ks * 8;
            unsigned a[4][4];
            #pragma unroll
            for (int mi = 0; mi < 4; mi++) {
                int r = wm*64 + mi*16 + g;
                a[mi][0] = __float_as_uint(Asb[(size_t)r*ASTR + kb + tg]);
                a[mi][1] = __float_as_uint(Asb[(size_t)(r+8)*ASTR + kb + tg]);
                a[mi][2] = __float_as_uint(Asb[(size_t)r*ASTR + kb + tg + 4]);
                a[mi][3] = __float_as_uint(Asb[(size_t)(r+8)*ASTR + kb + tg + 4]);
            }
            unsigned b[NI][2];
            #pragma unroll
            for (int ni = 0; ni < NI; ni++) {
                int c = wn*WN + ni*8 + g;
                b[ni][0] = __float_as_uint(Bsb[(size_t)(kb + tg)*BSTR + c]);
                b[ni][1] = __float_as_uint(Bsb[(size_t)(kb + tg + 4)*BSTR + c]);
            }
            #pragma unroll
            for (int mi = 0; mi < 4; mi++)
                #pragma unroll
                for (int ni = 0; ni < NI; ni++)
                    asm volatile(
                        "mma.sync.aligned.m16n8k8.row.col.f32.tf32.tf32.f32 "
                        "{%0,%1,%2,%3}, {%4,%5,%6,%7}, {%8,%9}, {%0,%1,%2,%3};"
                        : "+f"(acc[mi][ni][0]), "+f"(acc[mi][ni][1]),
                          "+f"(acc[mi][ni][2]), "+f"(acc[mi][ni][3])
                        : "r"(a[mi][0]), "r"(a[mi][1]), "r"(a[mi][2]), "r"(a[mi][3]),
                          "r"(b[ni][0]), "r"(b[ni][1]));
        }
        cp_wait0();
        __syncthreads();
    }

    #pragma unroll
    for (int mi = 0; mi < 4; mi++) {
        #pragma unroll
        for (int ni = 0; ni < NI; ni++) {
            int gr = bm0 + wm*64 + mi*16 + g;
            int gc = bn0 + wn*WN + ni*8 + tg*2;
            float bx = 0.f, by = 0.f;
            if (BIAS) { bx = bias[gc]; by = bias[gc+1]; }
            if (gr < M) {
                float2 v = { acc[mi][ni][0] + bx, acc[mi][ni][1] + by };
                *(float2*)&C[(size_t)gr*N + gc] = v;
            }
            if (gr + 8 < M) {
                float2 v = { acc[mi][ni][2] + bx, acc[mi][ni][3] + by };
                *(float2*)&C[(size_t)(gr+8)*N + gc] = v;
            }
        }
    }
}

// ---------------- attention projections -------------------------------------
__global__ void k_proj_heads(const float* __restrict__ ha) {
    int n = blockIdx.x;
    int w = threadIdx.x >> 5, l = threadIdx.x & 31;
    const float* row = g_hall + (size_t)n*HK + w*KK;
    const float* a = ha + w*(2*KK);
    float x0 = row[l], x1 = row[l+32];
    float s = x0*a[l]    + x1*a[l+32];
    float d = x0*a[64+l] + x1*a[96+l];
    #pragma unroll
    for (int off = 16; off; off >>= 1) {
        s += __shfl_xor_sync(0xffffffffu, s, off);
        d += __shfl_xor_sync(0xffffffffu, d, off);
    }
    if (l == 0) { g_ssrc[n*HH + w] = s; g_sdst[n*HH + w] = d; }
}

__global__ void k_proj_end(const float* __restrict__ ea) {
    int w = threadIdx.x >> 5, l = threadIdx.x & 31;
    int n = blockIdx.x * 8 + w;
    if (n >= NN) return;
    const float* row = g_h2 + (size_t)n*OO;
    float x0 = row[l], x1 = row[l+32];
    float s = x0*ea[l]    + x1*ea[l+32];
    float d = x0*ea[64+l] + x1*ea[96+l];
    #pragma unroll
    for (int off = 16; off; off >>= 1) {
        s += __shfl_xor_sync(0xffffffffu, s, off);
        d += __shfl_xor_sync(0xffffffffu, d, off);
    }
    if (l == 0) { g_s2s[n] = s; g_s2d[n] = d; }
}

// ---------------- layer-1 stats + normalized weights -------------------------
__global__ void k_stats1() {
    int w = threadIdx.x >> 5, l = threadIdx.x & 31;
    int n = blockIdx.x * 8 + w;
    if (n >= NN) return;
    int r0 = g_rowptr[n], r1 = g_rowptr[n+1];
    float sd[8];
    #pragma unroll
    for (int h = 0; h < 8; h++) sd[h] = g_sdst[n*8 + h];

    float m[8];
    #pragma unroll
    for (int h = 0; h < 8; h++) m[h] = -1e30f;
    for (int i = r0 + l; i < r1; i += 32) {
        int s = g_srt[i];
        float4 a0 = *(const float4*)&g_ssrc[s*8];
        float4 a1 = *(const float4*)&g_ssrc[s*8 + 4];
        float v[8] = { a0.x, a0.y, a0.z, a0.w, a1.x, a1.y, a1.z, a1.w };
        #pragma unroll
        for (int h = 0; h < 8; h++) m[h] = fmaxf(m[h], lrelu(v[h] + sd[h]));
    }
    #pragma unroll
    for (int h = 0; h < 8; h++)
        #pragma unroll
        for (int off = 16; off; off >>= 1)
            m[h] = fmaxf(m[h], __shfl_xor_sync(0xffffffffu, m[h], off));

    float sum[8];
    #pragma unroll
    for (int h = 0; h < 8; h++) sum[h] = 0.f;
    for (int i = r0 + l; i < r1; i += 32) {
        int s = g_srt[i];
        float4 a0 = *(const float4*)&g_ssrc[s*8];
        float4 a1 = *(const float4*)&g_ssrc[s*8 + 4];
        float v[8] = { a0.x, a0.y, a0.z, a0.w, a1.x, a1.y, a1.z, a1.w };
        #pragma unroll
        for (int h = 0; h < 8; h++) sum[h] += expf(lrelu(v[h] + sd[h]) - m[h]);
    }
    #pragma unroll
    for (int h = 0; h < 8; h++)
        #pragma unroll
        for (int off = 16; off; off >>= 1)
            sum[h] += __shfl_xor_sync(0xffffffffu, sum[h], off);

    float dinv[8];
    #pragma unroll
    for (int h = 0; h < 8; h++) dinv[h] = 1.f / (sum[h] + 1e-16f);

    // third pass: store normalized attention weights per head plane
    for (int i = r0 + l; i < r1; i += 32) {
        int s = g_srt[i];
        float4 a0 = *(const float4*)&g_ssrc[s*8];
        float4 a1 = *(const float4*)&g_ssrc[s*8 + 4];
        float v[8] = { a0.x, a0.y, a0.z, a0.w, a1.x, a1.y, a1.z, a1.w };
        #pragma unroll
        for (int h = 0; h < 8; h++)
            g_w[(size_t)h*EE + i] = expf(lrelu(v[h] + sd[h]) - m[h]) * dinv[h];
    }
}

// ---------------- layer-1 aggregation (warp/node, head/launch) ----------------
__global__ void k_agg1(int h) {
    int w = threadIdx.x >> 5, l = threadIdx.x & 31;
    int n = blockIdx.x * 8 + w;
    if (n >= NN) return;
    int r0 = g_rowptr[n], r1 = g_rowptr[n+1];
    const float* wp = g_w + (size_t)h*EE;
    float acc0 = 0.f, acc1 = 0.f;

    int i = r0;
    for (; i + 4 <= r1; i += 4) {
        int s0 = g_srt[i], s1 = g_srt[i+1], s2 = g_srt[i+2], s3 = g_srt[i+3];
        float w0 = wp[i], w1 = wp[i+1], w2 = wp[i+2], w3 = wp[i+3];
        const float* p0 = &g_hall[(size_t)s0*HK + h*KK];
        const float* p1 = &g_hall[(size_t)s1*HK + h*KK];
        const float* p2 = &g_hall[(size_t)s2*HK + h*KK];
        const float* p3 = &g_hall[(size_t)s3*HK + h*KK];
        float a0 = p0[l], b0 = p0[l+32];
        float a1 = p1[l], b1 = p1[l+32];
        float a2 = p2[l], b2 = p2[l+32];
        float a3 = p3[l], b3 = p3[l+32];
        acc0 = fmaf(w0, a0, acc0); acc1 = fmaf(w0, b0, acc1);
        acc0 = fmaf(w1, a1, acc0); acc1 = fmaf(w1, b1, acc1);
        acc0 = fmaf(w2, a2, acc0); acc1 = fmaf(w2, b2, acc1);
        acc0 = fmaf(w3, a3, acc0); acc1 = fmaf(w3, b3, acc1);
    }
    for (; i < r1; i++) {
        int s = g_srt[i];
        float wgt = wp[i];
        const float* p = &g_hall[(size_t)s*HK + h*KK];
        acc0 = fmaf(wgt, p[l],    acc0);
        acc1 = fmaf(wgt, p[l+32], acc1);
    }
    // tf32-round so GEMM2's truncating MMA is exact
    g_out1[(size_t)n*HK + h*KK + l]      = tf32r(elu(acc0));
    g_out1[(size_t)n*HK + h*KK + l + 32] = tf32r(elu(acc1));
}

// ---------------- layer-2 stats + weights ------------------------------------
__global__ void k_stats2() {
    int w = threadIdx.x >> 5, l = threadIdx.x & 31;
    int n = blockIdx.x * 8 + w;
    if (n >= NN) return;
    int r0 = g_rowptr[n], r1 = g_rowptr[n+1];
    float sd = g_s2d[n];
    float m = -1e30f;
    for (int i = r0 + l; i < r1; i += 32)
        m = fmaxf(m, lrelu(g_s2s[g_srt[i]] + sd));
    #pragma unroll
    for (int off = 16; off; off >>= 1)
        m = fmaxf(m, __shfl_xor_sync(0xffffffffu, m, off));
    float sum = 0.f;
    for (int i = r0 + l; i < r1; i += 32)
        sum += expf(lrelu(g_s2s[g_srt[i]] + sd) - m);
    #pragma unroll
    for (int off = 16; off; off >>= 1)
        sum += __shfl_xor_sync(0xffffffffu, sum, off);
    float dinv = 1.f / (sum + 1e-16f);
    for (int i = r0 + l; i < r1; i += 32)
        g_w2[i] = expf(lrelu(g_s2s[g_srt[i]] + sd) - m) * dinv;
}

// ---------------- layer-2 aggregation + elu + row softmax --------------------
__global__ void k_agg2(float* __restrict__ out) {
    int w = threadIdx.x >> 5, l = threadIdx.x & 31;
    int n = blockIdx.x * 8 + w;
    if (n >= NN) return;
    int r0 = g_rowptr[n], r1 = g_rowptr[n+1];
    float acc0 = 0.f, acc1 = 0.f;

    int i = r0;
    for (; i + 4 <= r1; i += 4) {
        int s0 = g_srt[i], s1 = g_srt[i+1], s2 = g_srt[i+2], s3 = g_srt[i+3];
        float w0 = g_w2[i], w1 = g_w2[i+1], w2 = g_w2[i+2], w3 = g_w2[i+3];
        const float* p0 = &g_h2[(size_t)s0*OO];
        const float* p1 = &g_h2[(size_t)s1*OO];
        const float* p2 = &g_h2[(size_t)s2*OO];
        const float* p3 = &g_h2[(size_t)s3*OO];
        float a0 = p0[l], b0 = p0[l+32];
        float a1 = p1[l], b1 = p1[l+32];
        float a2 = p2[l], b2 = p2[l+32];
        float a3 = p3[l], b3 = p3[l+32];
        acc0 = fmaf(w0, a0, acc0); acc1 = fmaf(w0, b0, acc1);
        acc0 = fmaf(w1, a1, acc0); acc1 = fmaf(w1, b1, acc1);
        acc0 = fmaf(w2, a2, acc0); acc1 = fmaf(w2, b2, acc1);
        acc0 = fmaf(w3, a3, acc0); acc1 = fmaf(w3, b3, acc1);
    }
    for (; i < r1; i++) {
        int s = g_srt[i];
        float wgt = g_w2[i];
        const float* p = &g_h2[(size_t)s*OO];
        acc0 = fmaf(wgt, p[l],    acc0);
        acc1 = fmaf(wgt, p[l+32], acc1);
    }
    float x0 = elu(acc0);
    float x1 = elu(acc1);
    float mx = fmaxf(x0, x1);
    #pragma unroll
    for (int off = 16; off; off >>= 1)
        mx = fmaxf(mx, __shfl_xor_sync(0xffffffffu, mx, off));
    float e0 = expf(x0 - mx), e1 = expf(x1 - mx);
    float sum = e0 + e1;
    #pragma unroll
    for (int off = 16; off; off >>= 1)
        sum += __shfl_xor_sync(0xffffffffu, sum, off);
    float inv = 1.f / sum;
    out[(size_t)n*OO + l]      = e0 * inv;
    out[(size_t)n*OO + l + 32] = e1 * inv;
}

// ---------------- driver ------------------------------------------------------
extern "C" void kernel_launch(void* const* d_in, const int* in_sizes, int n_in,
                              void* d_out, int out_size) {
    const float* x       = (const float*)d_in[0];
    const void*  edges   = d_in[1];
    const float* layer_W = (const float*)d_in[2];
    const float* layer_b = (const float*)d_in[3];
    const float* heads_W = (const float*)d_in[4];
    const float* heads_a = (const float*)d_in[5];
    const float* end_W   = (const float*)d_in[6];
    const float* end_a   = (const float*)d_in[7];
    float*       out     = (float*)d_out;

    float *p_Wc, *p_bc, *p_xt, *p_eWt, *p_hall, *p_out1, *p_h2;
    cudaGetSymbolAddress((void**)&p_Wc,   g_Wc);
    cudaGetSymbolAddress((void**)&p_bc,   g_bc);
    cudaGetSymbolAddress((void**)&p_xt,   g_xt);
    cudaGetSymbolAddress((void**)&p_eWt,  g_eWt);
    cudaGetSymbolAddress((void**)&p_hall, g_hall);
    cudaGetSymbolAddress((void**)&p_out1, g_out1);
    cudaGetSymbolAddress((void**)&p_h2,   g_h2);

    constexpr int SMEM1 = 2*(128*36 + 32*136)*4;  // 71680
    constexpr int SMEM2 = 2*(128*36 + 32*72)*4;   // 55296
    cudaFuncSetAttribute((const void*)k_mma<128,true>,
                         cudaFuncAttributeMaxDynamicSharedMemorySize, SMEM1);
    cudaFuncSetAttribute((const void*)k_mma<64,false>,
                         cudaFuncAttributeMaxDynamicSharedMemorySize, SMEM2);

    // --- CSR build -----------------------------------------------------------
    k_detect_edges<<<1, 256>>>((const unsigned*)edges);
    k_zero_deg<<<NB, 256>>>();
    k_conv_edges<<<(EE + 255)/256, 256>>>(edges);
    k_scan1<<<NB, 256>>>();
    k_scan2<<<1, 256>>>();
    k_scan3<<<NB, 256>>>();
    k_scatter<<<(EE + 255)/256, 256>>>();

    // --- weight prep ---------------------------------------------------------
    k_pack_wall<<<(DD*HK + 255)/256, 256>>>(heads_W);
    k_combine_W<<<DD, HK>>>(layer_W);
    k_combine_b<<<1, HK>>>(layer_b);
    k_cvt_x<<<(int)(((size_t)NN*DD/4 + 255)/256), 256>>>(x);
    k_cvt_ew<<<(HK*OO + 255)/256, 256>>>(end_W);

    // --- hall = x @ Wc + bc   [50000,256]x[256,512]  (tf32 MMA) --------------
    {
        dim3 grid(HK/128, (NN + 127)/128);
        k_mma<128,true><<<grid, 256, SMEM1>>>(NN, HK, DD, p_xt, p_Wc, p_bc, p_hall);
    }

    // --- layer 1 attention ---------------------------------------------------
    k_proj_heads<<<NN, 256>>>(heads_a);
    k_stats1<<<(NN + 7)/8, 256>>>();
    for (int h = 0; h < HH; h++)
        k_agg1<<<(NN + 7)/8, 256>>>(h);

    // --- h2 = hcat @ end_W    [50000,512]x[512,64]  (tf32 MMA) ---------------
    {
        dim3 grid(1, (NN + 127)/128);
        k_mma<64,false><<<grid, 256, SMEM2>>>(NN, OO, HK, p_out1, p_eWt, nullptr, p_h2);
    }

    // --- layer 2 attention + fused epilogue ----------------------------------
    k_proj_end<<<(NN + 7)/8, 256>>>(end_a);
    k_stats2<<<(NN + 7)/8, 256>>>();
    k_agg2<<<(NN + 7)/8, 256>>>(out);
}